// round 4
// baseline (speedup 1.0000x reference)
#include <cuda_runtime.h>
#include <cstdint>

// ---------------- problem constants ----------------
#define BATCHB   4
#define NANCH    230400        // 160*160*9
#define CAP      2048          // candidate capacity per image
#define NW       (CAP/32)      // 64 bitmap words
#define PCAP     4096          // conflict-pair capacity per image (~15x expected)
#define MAXD     1000
#define IMGW     1280.0f
#define TH_IOU   0.5f
#define ZTH      2.45f         // raw objectness gather threshold (sigmoid monotone)

// ---------------- device scratch (no allocations allowed) ----------------
__device__ unsigned long long g_keys [BATCHB][CAP];   // unsorted gathered keys
__device__ float4   g_boxes[BATCHB][CAP];             // unsorted decoded boxes
__device__ float    g_area [BATCHB][CAP];
__device__ float    g_score[BATCHB][CAP];
__device__ int      g_rank [BATCHB][CAP];             // rank (0 = best) per unsorted slot
__device__ unsigned g_pairs[BATCHB][PCAP];            // (i<<16)|j, key_i > key_j (i = suppressor)
__device__ int      g_counters[8];                    // [0..3] cand cnt, [4..7] pair cnt

// ---------------- helpers ----------------
__device__ __forceinline__ float4 decode_box(float4 d, float4 a) {
    float w  = a.z - a.x;
    float h  = a.w - a.y;
    float cx = a.x + 0.5f * w;
    float cy = a.y + 0.5f * h;
    float px = fmaf(d.x, w, cx);
    float py = fmaf(d.y, h, cy);
    float pw = expf(fminf(d.z, 4.0f)) * w;
    float ph = expf(fminf(d.w, 4.0f)) * h;
    float x1 = px - 0.5f * pw;
    float y1 = py - 0.5f * ph;
    float x2 = px + 0.5f * pw;
    float y2 = py + 0.5f * ph;
    x1 = fminf(fmaxf(x1, 0.0f), IMGW);
    x2 = fminf(fmaxf(x2, 0.0f), IMGW);
    y1 = fminf(fmaxf(y1, 0.0f), IMGW);
    y2 = fminf(fmaxf(y2, 0.0f), IMGW);
    return make_float4(x1, y1, x2, y2);
}

__device__ __forceinline__ float box_area(float4 b) {
    return fmaxf(b.z - b.x, 0.0f) * fmaxf(b.w - b.y, 0.0f);
}

// exact reference IoU decision: inter/(aA + aB - inter + 1e-9) > 0.5
// A/aA MUST be the suppressor (earlier-ranked) box to match operand order.
__device__ __forceinline__ bool conflict_ref(float4 A, float aA, float4 B, float aB) {
    float ix1 = fmaxf(A.x, B.x);
    float iy1 = fmaxf(A.y, B.y);
    float ix2 = fminf(A.z, B.z);
    float iy2 = fminf(A.w, B.w);
    float iw = ix2 - ix1, ih = iy2 - iy1;
    if (iw > 0.0f && ih > 0.0f) {
        float inter = iw * ih;
        return (inter / (aA + aB - inter + 1e-9f)) > TH_IOU;
    }
    return false;
}

// XLA expands lax.logistic as 0.5 + 0.5*tanh(0.5*x)
__device__ __forceinline__ float sigmoid_xla(float x) {
    return 0.5f + 0.5f * tanhf(0.5f * x);
}

// ---------------- kernel 1: gather + decode candidates above threshold ----------------
__global__ void __launch_bounds__(256) k_gather(
    const float* __restrict__ obj,
    const float* __restrict__ deltas,
    const float* __restrict__ anchors)
{
    int b = blockIdx.y;
    int i = blockIdx.x * blockDim.x + threadIdx.x;
    if (i >= NANCH) return;
    float x = obj[(long)b * NANCH + i];
    if (x <= ZTH) return;

    long base = ((long)b * NANCH + i);
    float4 d = reinterpret_cast<const float4*>(deltas)[base];
    float4 a = reinterpret_cast<const float4*>(anchors)[base];
    float4 bx = decode_box(d, a);
    if ((bx.z - bx.x >= 1.0f) && (bx.w - bx.y >= 1.0f)) {
        float s = sigmoid_xla(x);
        unsigned sb = __float_as_uint(s);           // positive float: bits monotone
        unsigned long long key =
            ((unsigned long long)sb << 18) | (unsigned long long)(0x3FFFFu - (unsigned)i);
        int p = atomicAdd(&g_counters[b], 1);
        if (p < CAP) {
            g_keys [b][p] = key;
            g_boxes[b][p] = bx;
            g_area [b][p] = box_area(bx);
            g_score[b][p] = s;
        }
    }
}

// ---------------- kernel 2: ranks + sparse conflict pairs (chip-wide) ----------------
// grid: (CAP/32 row-tiles, BATCHB), block 1024 = 32 warps; warp w owns row i.
__global__ void __launch_bounds__(1024) k_rankpairs()
{
    __shared__ unsigned long long skey[32];
    __shared__ float4 sbox[32];
    __shared__ float  sarea[32];

    const int b    = blockIdx.y;
    const int warp = threadIdx.x >> 5;
    const int lane = threadIdx.x & 31;

    int cand = g_counters[b]; if (cand > CAP) cand = CAP;
    if (blockIdx.x * 32 >= cand) return;        // uniform per block

    const int i = blockIdx.x * 32 + warp;
    const bool rv = (i < cand);                  // uniform per warp

    unsigned long long ki = 0;
    float4 A = make_float4(0.f, 0.f, 0.f, 0.f);
    float  aA = 0.f;
    if (rv) {
        ki = g_keys[b][i];
        A  = g_boxes[b][i];
        aA = g_area[b][i];
    }

    int rank = 0;
    const int ntile = (cand + 31) >> 5;
    for (int w = 0; w < ntile; ++w) {
        __syncthreads();
        if (threadIdx.x < 32) {
            int j = w * 32 + threadIdx.x;
            if (j < cand) {
                skey[threadIdx.x] = g_keys[b][j];
                sbox[threadIdx.x] = g_boxes[b][j];
                sarea[threadIdx.x] = g_area[b][j];
            } else {
                skey[threadIdx.x] = 0ULL;
                sarea[threadIdx.x] = 0.f;
                sbox[threadIdx.x] = make_float4(0.f, 0.f, 0.f, 0.f);
            }
        }
        __syncthreads();
        if (rv) {
            int j = w * 32 + lane;
            bool jv = (j < cand);
            unsigned long long kj = skey[lane];
            bool gt = jv && (kj > ki);
            rank += __popc(__ballot_sync(0xFFFFFFFFu, gt));
            if (jv && (ki > kj) && conflict_ref(A, aA, sbox[lane], sarea[lane])) {
                int p = atomicAdd(&g_counters[4 + b], 1);
                if (p < PCAP)
                    g_pairs[b][p] = ((unsigned)i << 16) | (unsigned)j;
            }
        }
    }
    if (rv && lane == 0) g_rank[b][i] = rank;
}

// ---------------- kernel 3: parallel greedy fixpoint + output ----------------
__global__ void __launch_bounds__(1024, 1) k_scan(float* __restrict__ out, int out_size)
{
    __shared__ int           rnk[CAP];
    __shared__ unsigned      spairs[PCAP];      // (rank_i << 16) | rank_j, rank_i < rank_j
    __shared__ unsigned char state[CAP];        // 0 = UNK, 1 = SELECTED, 2 = DEAD
    __shared__ unsigned char hasLive[CAP];
    __shared__ unsigned      selW[NW];
    __shared__ int           wordPref[NW];
    __shared__ int           sChanged;

    const int b   = blockIdx.x;
    const int tid = threadIdx.x;

    int cand = g_counters[b];     if (cand > CAP)  cand = CAP;
    int np   = g_counters[4 + b]; if (np   > PCAP) np   = PCAP;

    // load ranks; init state (ranks >= cand start DEAD so they never get selected)
    #pragma unroll
    for (int rep = 0; rep < 2; ++rep) {
        int u = tid + rep * 1024;
        rnk[u]   = (u < cand) ? g_rank[b][u] : 0;
        state[u] = (u < cand) ? 0 : 2;
    }
    __syncthreads();

    // re-encode pairs into rank space
    for (int p = tid; p < np; p += 1024) {
        unsigned pr = g_pairs[b][p];
        unsigned ri = (unsigned)rnk[pr >> 16];
        unsigned rj = (unsigned)rnk[pr & 0xFFFFu];
        spairs[p] = (ri << 16) | rj;
    }
    __syncthreads();

    // fixpoint rounds: SELECTED(j) <=> all suppressors DEAD; DEAD(j) <=> some suppressor SELECTED.
    // Suppressor rank < suppressed rank => DAG => unique fixpoint == greedy NMS.
    while (true) {
        if (tid == 0) sChanged = 0;
        hasLive[tid] = 0; hasLive[tid + 1024] = 0;
        __syncthreads();

        // kill targets of currently-SELECTED suppressors
        for (int p = tid; p < np; p += 1024) {
            unsigned pr = spairs[p];
            unsigned ri = pr >> 16, rj = pr & 0xFFFFu;
            if (state[ri] == 1 && state[rj] == 0) state[rj] = 2;
        }
        __syncthreads();

        // mark UNK candidates that still have a live (non-DEAD) suppressor
        for (int p = tid; p < np; p += 1024) {
            unsigned pr = spairs[p];
            unsigned ri = pr >> 16, rj = pr & 0xFFFFu;
            if (state[rj] == 0 && state[ri] != 2) hasLive[rj] = 1;
        }
        __syncthreads();

        // promote UNK candidates with no live suppressor
        #pragma unroll
        for (int rep = 0; rep < 2; ++rep) {
            int r = tid + rep * 1024;
            if (state[r] == 0 && !hasLive[r]) { state[r] = 1; sChanged = 1; }
        }
        __syncthreads();
        if (!sChanged) break;
        __syncthreads();
    }

    // build selection bitmap over ranks
    if (tid < CAP / 32 * 1) { /* no-op shape hint */ }
    {
        // each of the first 64 warps builds one word; we have 32 warps -> 2 words each
        int lane = tid & 31, wid = tid >> 5;
        #pragma unroll
        for (int rep = 0; rep < 2; ++rep) {
            int w = wid + rep * 32;
            int r = w * 32 + lane;
            unsigned bal = __ballot_sync(0xFFFFFFFFu, state[r] == 1);
            if (lane == 0) selW[w] = bal;
        }
    }
    __syncthreads();
    if (tid == 0) {
        int run = 0;
        #pragma unroll
        for (int w = 0; w < NW; ++w) { wordPref[w] = run; run += __popc(selW[w]); }
    }
    __syncthreads();

    // ---- output: boxes [B,1000,4] | scores [B,1000] | valid [B,1000], all f32 ----
    const int scoresO = BATCHB * MAXD * 4;
    const int validO  = scoresO + BATCHB * MAXD;

    // zero-fill this image's slots
    for (int s = tid; s < MAXD; s += 1024) {
        int bb = (b * MAXD + s) * 4;
        if (bb + 3 < out_size) {
            out[bb + 0] = 0.f; out[bb + 1] = 0.f;
            out[bb + 2] = 0.f; out[bb + 3] = 0.f;
        }
        int so = scoresO + b * MAXD + s;
        if (so < out_size) out[so] = 0.f;
        int vo = validO + b * MAXD + s;
        if (vo < out_size) out[vo] = 0.f;
    }
    __syncthreads();

    // emit selected: slot = rank order among selected (== reference selection order)
    #pragma unroll
    for (int rep = 0; rep < 2; ++rep) {
        int u = tid + rep * 1024;
        if (u < cand) {
            int r = rnk[u];
            unsigned wbits = selW[r >> 5];
            if ((wbits >> (r & 31)) & 1u) {
                int slot = wordPref[r >> 5] + __popc(wbits & ((1u << (r & 31)) - 1u));
                if (slot < MAXD) {
                    float4 bx = g_boxes[b][u];
                    int bb = (b * MAXD + slot) * 4;
                    if (bb + 3 < out_size) {
                        out[bb + 0] = bx.x;
                        out[bb + 1] = bx.y;
                        out[bb + 2] = bx.z;
                        out[bb + 3] = bx.w;
                    }
                    int so = scoresO + b * MAXD + slot;
                    if (so < out_size) out[so] = g_score[b][u];
                    int vo = validO + b * MAXD + slot;
                    if (vo < out_size) out[vo] = 1.0f;
                }
            }
        }
    }
}

// ---------------- host launcher ----------------
extern "C" void kernel_launch(void* const* d_in, const int* in_sizes, int n_in,
                              void* d_out, int out_size)
{
    const float* obj     = (const float*)d_in[0];
    const float* deltas  = (const float*)d_in[1];
    const float* anchors = (const float*)d_in[2];
    float* out = (float*)d_out;

    // reset candidate + pair counters (graph-capturable memset)
    void* cntAddr = nullptr;
    cudaGetSymbolAddress(&cntAddr, g_counters);
    cudaMemsetAsync(cntAddr, 0, sizeof(int) * 8, 0);

    // gather + decode candidates
    {
        dim3 grid((NANCH + 255) / 256, BATCHB);
        k_gather<<<grid, 256>>>(obj, deltas, anchors);
    }

    // chip-wide ranks + sparse conflict pairs
    {
        dim3 grid(CAP / 32, BATCHB);
        k_rankpairs<<<grid, 1024>>>();
    }

    // parallel greedy fixpoint + output
    k_scan<<<BATCHB, 1024>>>(out, out_size);
}

// round 5
// speedup vs baseline: 2.6380x; 2.6380x over previous
#include <cuda_runtime.h>
#include <cstdint>

// ---------------- problem constants ----------------
#define BATCHB   4
#define NANCH    230400        // 160*160*9
#define CAP      2048          // candidate capacity per image
#define NW       (CAP/32)      // 64 bitmap words
#define PCAP     4096          // conflict-pair capacity per image (~15x expected)
#define MAXD     1000
#define IMGW     1280.0f
#define TH_IOU   0.5f
#define ZTH      2.45f         // raw objectness gather threshold (sigmoid monotone)

// ---------------- device scratch (no allocations allowed) ----------------
__device__ unsigned long long g_keys [BATCHB][CAP];   // unsorted gathered keys
__device__ float4   g_boxes[BATCHB][CAP];             // unsorted decoded boxes
__device__ float    g_area [BATCHB][CAP];
__device__ float    g_score[BATCHB][CAP];
__device__ int      g_rank [BATCHB][CAP];             // rank (0 = best) per unsorted slot
__device__ unsigned g_pairs[BATCHB][PCAP];            // (i<<16)|j, key_i > key_j (i = suppressor)
__device__ int      g_counters[8];                    // [0..3] cand cnt, [4..7] pair cnt

// ---------------- helpers ----------------
__device__ __forceinline__ float4 decode_box(float4 d, float4 a) {
    float w  = a.z - a.x;
    float h  = a.w - a.y;
    float cx = a.x + 0.5f * w;
    float cy = a.y + 0.5f * h;
    float px = fmaf(d.x, w, cx);
    float py = fmaf(d.y, h, cy);
    float pw = expf(fminf(d.z, 4.0f)) * w;
    float ph = expf(fminf(d.w, 4.0f)) * h;
    float x1 = px - 0.5f * pw;
    float y1 = py - 0.5f * ph;
    float x2 = px + 0.5f * pw;
    float y2 = py + 0.5f * ph;
    x1 = fminf(fmaxf(x1, 0.0f), IMGW);
    x2 = fminf(fmaxf(x2, 0.0f), IMGW);
    y1 = fminf(fmaxf(y1, 0.0f), IMGW);
    y2 = fminf(fmaxf(y2, 0.0f), IMGW);
    return make_float4(x1, y1, x2, y2);
}

__device__ __forceinline__ float box_area(float4 b) {
    return fmaxf(b.z - b.x, 0.0f) * fmaxf(b.w - b.y, 0.0f);
}

// exact reference IoU decision: inter/(aA + aB - inter + 1e-9) > 0.5
// A/aA MUST be the suppressor (earlier-ranked) box to match operand order.
__device__ __forceinline__ bool conflict_ref(float4 A, float aA, float4 B, float aB) {
    float ix1 = fmaxf(A.x, B.x);
    float iy1 = fmaxf(A.y, B.y);
    float ix2 = fminf(A.z, B.z);
    float iy2 = fminf(A.w, B.w);
    float iw = ix2 - ix1, ih = iy2 - iy1;
    if (iw > 0.0f && ih > 0.0f) {
        float inter = iw * ih;
        return (inter / (aA + aB - inter + 1e-9f)) > TH_IOU;
    }
    return false;
}

// XLA expands lax.logistic as 0.5 + 0.5*tanh(0.5*x)
__device__ __forceinline__ float sigmoid_xla(float x) {
    return 0.5f + 0.5f * tanhf(0.5f * x);
}

// ---------------- kernel 1: gather + decode (4 anchors/thread, float4 reads) ----------------
__global__ void __launch_bounds__(256) k_gather(
    const float* __restrict__ obj,
    const float* __restrict__ deltas,
    const float* __restrict__ anchors)
{
    int b  = blockIdx.y;
    int q  = blockIdx.x * blockDim.x + threadIdx.x;   // quad index
    if (q >= NANCH / 4) return;

    float4 xs = reinterpret_cast<const float4*>(obj + (long)b * NANCH)[q];
    float xv[4] = {xs.x, xs.y, xs.z, xs.w};

    #pragma unroll
    for (int k = 0; k < 4; ++k) {
        float x = xv[k];
        if (x <= ZTH) continue;
        int i = q * 4 + k;
        long base = ((long)b * NANCH + i);
        float4 d = reinterpret_cast<const float4*>(deltas)[base];
        float4 a = reinterpret_cast<const float4*>(anchors)[base];
        float4 bx = decode_box(d, a);
        if ((bx.z - bx.x >= 1.0f) && (bx.w - bx.y >= 1.0f)) {
            float s = sigmoid_xla(x);
            unsigned sb = __float_as_uint(s);       // positive float: bits monotone
            unsigned long long key =
                ((unsigned long long)sb << 18) | (unsigned long long)(0x3FFFFu - (unsigned)i);
            int p = atomicAdd(&g_counters[b], 1);
            if (p < CAP) {
                g_keys [b][p] = key;
                g_boxes[b][p] = bx;
                g_area [b][p] = box_area(bx);
                g_score[b][p] = s;
            }
        }
    }
}

// ---------------- kernel 2: ranks + sparse conflict pairs (barrier-free streaming) ----------------
// grid: (CAP/8, BATCHB), block 256 = 8 warps; warp w owns row i. All loads hit L1/L2.
__global__ void __launch_bounds__(256) k_rankpairs()
{
    const int b    = blockIdx.y;
    const int warp = threadIdx.x >> 5;
    const int lane = threadIdx.x & 31;

    int cand = g_counters[b]; if (cand > CAP) cand = CAP;
    const int i = blockIdx.x * 8 + warp;
    if (i >= cand) return;

    const unsigned long long ki = g_keys[b][i];   // broadcast load
    const float4 A  = g_boxes[b][i];
    const float  aA = g_area[b][i];

    int rank = 0;
    for (int jt = 0; jt < cand; jt += 32) {
        int j = jt + lane;
        bool jv = (j < cand);
        unsigned long long kj = jv ? g_keys[b][j] : 0ULL;
        bool gt = jv && (kj > ki);
        rank += __popc(__ballot_sync(0xFFFFFFFFu, gt));
        if (jv && (ki > kj)) {
            float4 B = g_boxes[b][j];
            float aB = g_area[b][j];
            if (conflict_ref(A, aA, B, aB)) {
                int p = atomicAdd(&g_counters[4 + b], 1);
                if (p < PCAP)
                    g_pairs[b][p] = ((unsigned)i << 16) | (unsigned)j;
            }
        }
    }
    if (lane == 0) g_rank[b][i] = rank;
}

// ---------------- kernel 3: parallel greedy fixpoint + output ----------------
__global__ void __launch_bounds__(1024, 1) k_scan(float* __restrict__ out, int out_size)
{
    __shared__ int           rnk[CAP];
    __shared__ unsigned      spairs[PCAP];      // (rank_i << 16) | rank_j, rank_i < rank_j
    __shared__ unsigned char state[CAP];        // 0 = UNK, 1 = SELECTED, 2 = DEAD
    __shared__ unsigned char hasLive[CAP];
    __shared__ unsigned      selW[NW];
    __shared__ int           wordPref[NW];
    __shared__ int           sChanged;

    const int b   = blockIdx.x;
    const int tid = threadIdx.x;

    int cand = g_counters[b];     if (cand > CAP)  cand = CAP;
    int np   = g_counters[4 + b]; if (np   > PCAP) np   = PCAP;

    // load ranks; state indexed by RANK: ranks are a permutation of [0, cand)
    #pragma unroll
    for (int rep = 0; rep < 2; ++rep) {
        int u = tid + rep * 1024;
        rnk[u]   = (u < cand) ? g_rank[b][u] : 0;
        state[u] = (u < cand) ? 0 : 2;
    }
    __syncthreads();

    // re-encode pairs into rank space
    for (int p = tid; p < np; p += 1024) {
        unsigned pr = g_pairs[b][p];
        unsigned ri = (unsigned)rnk[pr >> 16];
        unsigned rj = (unsigned)rnk[pr & 0xFFFFu];
        spairs[p] = (ri << 16) | rj;
    }
    __syncthreads();

    // fixpoint rounds: SELECTED(j) <=> all suppressors DEAD; DEAD(j) <=> some suppressor SELECTED.
    // Suppressor rank < suppressed rank => DAG => unique fixpoint == greedy NMS.
    while (true) {
        if (tid == 0) sChanged = 0;
        hasLive[tid] = 0; hasLive[tid + 1024] = 0;
        __syncthreads();

        // kill targets of currently-SELECTED suppressors
        for (int p = tid; p < np; p += 1024) {
            unsigned pr = spairs[p];
            unsigned ri = pr >> 16, rj = pr & 0xFFFFu;
            if (state[ri] == 1 && state[rj] == 0) state[rj] = 2;
        }
        __syncthreads();

        // mark UNK candidates that still have a live (non-DEAD) suppressor
        for (int p = tid; p < np; p += 1024) {
            unsigned pr = spairs[p];
            unsigned ri = pr >> 16, rj = pr & 0xFFFFu;
            if (state[rj] == 0 && state[ri] != 2) hasLive[rj] = 1;
        }
        __syncthreads();

        // promote UNK candidates with no live suppressor
        #pragma unroll
        for (int rep = 0; rep < 2; ++rep) {
            int r = tid + rep * 1024;
            if (state[r] == 0 && !hasLive[r]) { state[r] = 1; sChanged = 1; }
        }
        __syncthreads();
        if (!sChanged) break;
        __syncthreads();
    }

    // build selection bitmap over ranks (32 warps -> 2 words each)
    {
        int lane = tid & 31, wid = tid >> 5;
        #pragma unroll
        for (int rep = 0; rep < 2; ++rep) {
            int w = wid + rep * 32;
            int r = w * 32 + lane;
            unsigned bal = __ballot_sync(0xFFFFFFFFu, state[r] == 1);
            if (lane == 0) selW[w] = bal;
        }
    }
    __syncthreads();
    if (tid == 0) {
        int run = 0;
        #pragma unroll
        for (int w = 0; w < NW; ++w) { wordPref[w] = run; run += __popc(selW[w]); }
    }
    __syncthreads();

    // ---- output: boxes [B,1000,4] | scores [B,1000] | valid [B,1000], all f32 ----
    const int scoresO = BATCHB * MAXD * 4;
    const int validO  = scoresO + BATCHB * MAXD;

    // zero-fill this image's slots
    for (int s = tid; s < MAXD; s += 1024) {
        int bb = (b * MAXD + s) * 4;
        if (bb + 3 < out_size) {
            out[bb + 0] = 0.f; out[bb + 1] = 0.f;
            out[bb + 2] = 0.f; out[bb + 3] = 0.f;
        }
        int so = scoresO + b * MAXD + s;
        if (so < out_size) out[so] = 0.f;
        int vo = validO + b * MAXD + s;
        if (vo < out_size) out[vo] = 0.f;
    }
    __syncthreads();

    // emit selected: slot = rank order among selected (== reference selection order)
    #pragma unroll
    for (int rep = 0; rep < 2; ++rep) {
        int u = tid + rep * 1024;
        if (u < cand) {
            int r = rnk[u];
            unsigned wbits = selW[r >> 5];
            if ((wbits >> (r & 31)) & 1u) {
                int slot = wordPref[r >> 5] + __popc(wbits & ((1u << (r & 31)) - 1u));
                if (slot < MAXD) {
                    float4 bx = g_boxes[b][u];
                    int bb = (b * MAXD + slot) * 4;
                    if (bb + 3 < out_size) {
                        out[bb + 0] = bx.x;
                        out[bb + 1] = bx.y;
                        out[bb + 2] = bx.z;
                        out[bb + 3] = bx.w;
                    }
                    int so = scoresO + b * MAXD + slot;
                    if (so < out_size) out[so] = g_score[b][u];
                    int vo = validO + b * MAXD + slot;
                    if (vo < out_size) out[vo] = 1.0f;
                }
            }
        }
    }
}

// ---------------- host launcher ----------------
extern "C" void kernel_launch(void* const* d_in, const int* in_sizes, int n_in,
                              void* d_out, int out_size)
{
    const float* obj     = (const float*)d_in[0];
    const float* deltas  = (const float*)d_in[1];
    const float* anchors = (const float*)d_in[2];
    float* out = (float*)d_out;

    // reset candidate + pair counters (graph-capturable memset)
    void* cntAddr = nullptr;
    cudaGetSymbolAddress(&cntAddr, g_counters);
    cudaMemsetAsync(cntAddr, 0, sizeof(int) * 8, 0);

    // gather + decode candidates (4 anchors per thread)
    {
        dim3 grid((NANCH / 4 + 255) / 256, BATCHB);
        k_gather<<<grid, 256>>>(obj, deltas, anchors);
    }

    // chip-wide ranks + sparse conflict pairs (barrier-free)
    {
        dim3 grid(CAP / 8, BATCHB);
        k_rankpairs<<<grid, 256>>>();
    }

    // parallel greedy fixpoint + output
    k_scan<<<BATCHB, 1024>>>(out, out_size);
}